// round 4
// baseline (speedup 1.0000x reference)
#include <cuda_runtime.h>
#include <cuda_bf16.h>

// Problem constants
#define Hc 200          // H
#define Wc 196          // W
#define NPIX (Hc * Wc)  // 39200 pixels per camera
#define NPIX4 (NPIX / 4)// 9800
#define NCH 256
#define NCAM 6
#define SSZ 400
#define NCELL (SSZ * SSZ)  // 160000

// Scratch (allocation-free rule). Zero-initialized at module load; finalize
// kernel restores them to zero after each run, so they are zero at every
// kernel_launch entry (correctness run and all graph replays).
__device__ float g_sum[NCELL];
__device__ float g_cnt[NCELL];
__device__ int   g_mask_flags;   // bit0: u8 evidence, bit1: f32 evidence (idempotent OR)

typedef unsigned long long ull;

__device__ __forceinline__ ull pack2(float lo, float hi) {
    ull r;
    asm("mov.b64 %0, {%1, %2};" : "=l"(r) : "f"(lo), "f"(hi));
    return r;
}
__device__ __forceinline__ void unpack2(float& lo, float& hi, ull v) {
    asm("mov.b64 {%0, %1}, %2;" : "=f"(lo), "=f"(hi) : "l"(v));
}
__device__ __forceinline__ void ffma2(ull& d, ull a, ull b, ull c) {
    asm("fma.rn.f32x2 %0, %1, %2, %3;" : "=l"(d) : "l"(a), "l"(b), "l"(c));
}

// Mask dtype fingerprint: 9800 words cover the buffer whether it is u8 (9800
// words), i32 or f32 (39200 words; first 9800 suffice). One word per thread.
__global__ void detect_kernel(const unsigned int* __restrict__ mask_words) {
    int gid = blockIdx.x * 256 + threadIdx.x;
    unsigned int local = 0;
    if (gid < NPIX4) {
        unsigned int v = mask_words[gid];
        if (v == 0x3F800000u) local = 2;                         // float 1.0f
        else if ((v & ~0x01010101u) == 0u && (v & 0xFFFFFF00u))  // packed bools
            local = 1;
    }
    unsigned int r = __reduce_or_sync(0xFFFFFFFFu, local);
    if ((threadIdx.x & 31) == 0 && r) atomicOr(&g_mask_flags, (int)r);
}

// 4 pixels per thread via float4; pixels are contiguous in memory (pix = w*H+h).
// Channel loop streams the 241MB tensor fully coalesced (16B/thread/iter).
// Packed f32x2 FMAs halve scalar-FMA issue pressure (mem/FMA were co-bound).
__global__ __launch_bounds__(256) void bev_dot_scatter_kernel(
    const float* __restrict__ feats,   // [NCAM, NCH, Wc, Hc]
    const float* __restrict__ mats,    // [NCAM, 4, 4]
    const float* __restrict__ lc,      // [4, NPIX], n = h*W + w
    const void*  __restrict__ mask_raw,
    const float* __restrict__ w_cls)
{
    __shared__ ull   swd[NCH];   // (w, w) packed per channel
    __shared__ float sm[8];      // rows 0,1 of this cam's 4x4

    const int tid = threadIdx.x;
    const int cam = blockIdx.y;

    {
        float w = w_cls[tid];
        swd[tid] = pack2(w, w);
    }
    if (tid < 8) sm[tid] = mats[cam * 16 + tid];
    __syncthreads();

    const int pix4 = blockIdx.x * 256 + tid;
    if (pix4 >= NPIX4) return;

    const float4* p4 = (const float4*)(feats + (size_t)cam * NCH * NPIX) + pix4;

    ull acc01 = 0, acc23 = 0;
#pragma unroll 8
    for (int ch = 0; ch < NCH; ch++) {
        float4 v = p4[(size_t)ch * NPIX4];
        ull w2 = swd[ch];
        ffma2(acc01, pack2(v.x, v.y), w2, acc01);
        ffma2(acc23, pack2(v.z, v.w), w2, acc23);
    }
    float d0, d1, d2, d3;
    unpack2(d0, d1, acc01);
    unpack2(d2, d3, acc23);
    float dots[4] = {d0, d1, d2, d3};

    // pix = 4*pix4 + j ; Hc=200 divisible by 4 -> all 4 share the same column wq
    const int pix0 = pix4 * 4;
    const int wq = pix0 / Hc;
    const int h0 = pix0 - wq * Hc;

    const int flags = g_mask_flags;
    const float m00 = sm[0], m01 = sm[1], m03 = sm[3];
    const float m10 = sm[4], m11 = sm[5], m13 = sm[7];

#pragma unroll
    for (int j = 0; j < 4; j++) {
        const int n = (h0 + j) * Wc + wq;
        bool m;
        if (flags & 2)      m = ((const float*)mask_raw)[n] != 0.0f;
        else if (flags & 1) m = ((const unsigned char*)mask_raw)[n] != 0;
        else                m = ((const int*)mask_raw)[n] != 0;
        if (!m) continue;

        const float gx = lc[n];
        const float gy = lc[NPIX + n];
        const float x = m00 * gx + m01 * gy + m03;
        const float y = m10 * gx + m11 * gy + m13;
        // (coord + 100) / 0.5 == (coord + 100) * 2 exactly; jnp.round == rintf
        const float fx = rintf((x + 100.0f) * 2.0f);
        const float fy = rintf((y + 100.0f) * 2.0f);
        if (fx >= 0.0f && fx < (float)SSZ && fy >= 0.0f && fy < (float)SSZ) {
            const int cell = (int)fx * SSZ + (int)fy;
            atomicAdd(&g_sum[cell], dots[j]);
            atomicAdd(&g_cnt[cell], 1.0f);
        }
    }
}

// Finalize AND restore scratch to zero for the next run (graph replay invariant).
__global__ void finalize_kernel(float* __restrict__ out,
                                const float* __restrict__ b_cls) {
    int i4 = blockIdx.x * 256 + threadIdx.x;
    if (i4 >= NCELL / 4) return;
    float4* s4 = (float4*)g_sum + i4;
    float4* c4 = (float4*)g_cnt + i4;
    float4 s = *s4;
    float4 c = *c4;
    const float b = b_cls[0];
    float4 o;
    // where(cnt>=1, sum/max(cnt,1), sum) == sum/max(cnt,1): sum==0 when cnt==0
    o.x = s.x / fmaxf(c.x, 1.0f) + b;
    o.y = s.y / fmaxf(c.y, 1.0f) + b;
    o.z = s.z / fmaxf(c.z, 1.0f) + b;
    o.w = s.w / fmaxf(c.w, 1.0f) + b;
    ((float4*)out)[i4] = o;
    float4 z = make_float4(0.f, 0.f, 0.f, 0.f);
    *s4 = z;
    *c4 = z;
}

extern "C" void kernel_launch(void* const* d_in, const int* in_sizes, int n_in,
                              void* d_out, int out_size) {
    // Resolve inputs by element count (all distinct) — robust to metadata order.
    const float* feats = 0; const float* mats = 0; const float* lc = 0;
    const void*  mask  = 0; const float* w_cls = 0; const float* b_cls = 0;
    for (int i = 0; i < n_in; i++) {
        switch (in_sizes[i]) {
            case 60211200: feats = (const float*)d_in[i]; break;
            case 96:       mats  = (const float*)d_in[i]; break;
            case 156800:   lc    = (const float*)d_in[i]; break;
            case 39200:    mask  = d_in[i];               break;
            case 256:      w_cls = (const float*)d_in[i]; break;
            case 1:        b_cls = (const float*)d_in[i]; break;
        }
    }
    float* out = (float*)d_out;

    detect_kernel<<<(NPIX4 + 255) / 256, 256>>>((const unsigned int*)mask);

    dim3 grid((NPIX4 + 255) / 256, NCAM);   // 39 x 6 = 234 blocks, all resident
    bev_dot_scatter_kernel<<<grid, 256>>>(feats, mats, lc, mask, w_cls);

    finalize_kernel<<<(NCELL / 4 + 255) / 256, 256>>>(out, b_cls);
}

// round 5
// speedup vs baseline: 1.1293x; 1.1293x over previous
#include <cuda_runtime.h>
#include <cuda_bf16.h>

// Problem constants
#define Hc 200          // H
#define Wc 196          // W
#define NPIX (Hc * Wc)  // 39200 pixels per camera
#define NPIX4 (NPIX / 4)// 9800
#define NCH 256
#define NCHUNK 4
#define CHCH (NCH / NCHUNK)  // 64 channels per chunk
#define NCAM 6
#define SSZ 400
#define NCELL (SSZ * SSZ)    // 160000

// Scratch (allocation-free rule). Zero at module load; finalize re-zeros after
// reading, so the grids are zero at every kernel_launch entry (correctness run
// and every graph replay).
__device__ float g_sum[NCELL];
__device__ float g_cnt[NCELL];

typedef unsigned long long ull;

__device__ __forceinline__ ull pack2(float lo, float hi) {
    ull r;
    asm("mov.b64 %0, {%1, %2};" : "=l"(r) : "f"(lo), "f"(hi));
    return r;
}
__device__ __forceinline__ void unpack2(float& lo, float& hi, ull v) {
    asm("mov.b64 {%0, %1}, %2;" : "=f"(lo), "=f"(hi) : "l"(v));
}
__device__ __forceinline__ void ffma2(ull& d, ull a, ull b, ull c) {
    asm("fma.rn.f32x2 %0, %1, %2, %3;" : "=l"(d) : "l"(a), "l"(b), "l"(c));
}

// Grid: (pix4 tiles, cam, channel-chunk). Each thread owns 4 contiguous pixels
// (one float4 per channel) and a 64-channel slice; partial dots are scattered
// with atomics (scatter-add is linear in channels). Chunk 0 also adds counts.
// Mask is read as a 32-bit word: correct for int32 AND float32 bool storage
// (true is nonzero in both); u8 storage ruled out empirically in R1.
__global__ __launch_bounds__(128) void bev_dot_scatter_kernel(
    const float* __restrict__ feats,   // [NCAM, NCH, Wc, Hc]
    const float* __restrict__ mats,    // [NCAM, 4, 4]
    const float* __restrict__ lc,      // [4, NPIX], n = h*W + w
    const int*   __restrict__ mask,    // [NPIX] bool stored as 32-bit words
    const float* __restrict__ w_cls)   // [NCH]
{
    __shared__ ull   swd[CHCH];  // (w, w) packed, this chunk's 64 channels
    __shared__ float sm[8];      // rows 0,1 of this cam's 4x4

    const int tid   = threadIdx.x;
    const int cam   = blockIdx.y;
    const int chunk = blockIdx.z;

    if (tid < CHCH) {
        float w = w_cls[chunk * CHCH + tid];
        swd[tid] = pack2(w, w);
    }
    if (tid < 8) sm[tid] = mats[cam * 16 + tid];
    __syncthreads();

    const int pix4 = blockIdx.x * 128 + tid;
    if (pix4 >= NPIX4) return;

    const float4* p4 = (const float4*)(feats + (size_t)cam * NCH * NPIX)
                       + (size_t)chunk * CHCH * NPIX4 + pix4;

    ull acc01 = 0, acc23 = 0;
#pragma unroll 8
    for (int ch = 0; ch < CHCH; ch++) {
        float4 v = p4[(size_t)ch * NPIX4];
        ull w2 = swd[ch];
        ffma2(acc01, pack2(v.x, v.y), w2, acc01);
        ffma2(acc23, pack2(v.z, v.w), w2, acc23);
    }
    float d0, d1, d2, d3;
    unpack2(d0, d1, acc01);
    unpack2(d2, d3, acc23);
    float dots[4] = {d0, d1, d2, d3};

    // pix = 4*pix4 + j ; Hc divisible by 4 -> all 4 pixels share column wq
    const int pix0 = pix4 * 4;
    const int wq = pix0 / Hc;
    const int h0 = pix0 - wq * Hc;

    const float m00 = sm[0], m01 = sm[1], m03 = sm[3];
    const float m10 = sm[4], m11 = sm[5], m13 = sm[7];

#pragma unroll
    for (int j = 0; j < 4; j++) {
        const int n = (h0 + j) * Wc + wq;
        if (mask[n] == 0) continue;

        const float gx = lc[n];
        const float gy = lc[NPIX + n];
        const float x = m00 * gx + m01 * gy + m03;
        const float y = m10 * gx + m11 * gy + m13;
        // (coord + 100) / 0.5 == (coord + 100) * 2 exactly; jnp.round == rintf
        const float fx = rintf((x + 100.0f) * 2.0f);
        const float fy = rintf((y + 100.0f) * 2.0f);
        if (fx >= 0.0f && fx < (float)SSZ && fy >= 0.0f && fy < (float)SSZ) {
            const int cell = (int)fx * SSZ + (int)fy;
            atomicAdd(&g_sum[cell], dots[j]);
            if (chunk == 0) atomicAdd(&g_cnt[cell], 1.0f);
        }
    }
}

// Finalize AND restore scratch to zero for the next run (graph replay invariant).
__global__ void finalize_kernel(float* __restrict__ out,
                                const float* __restrict__ b_cls) {
    int i4 = blockIdx.x * 256 + threadIdx.x;
    if (i4 >= NCELL / 4) return;
    float4* s4 = (float4*)g_sum + i4;
    float4* c4 = (float4*)g_cnt + i4;
    float4 s = *s4;
    float4 c = *c4;
    const float b = b_cls[0];
    float4 o;
    // where(cnt>=1, sum/max(cnt,1), sum) == sum/max(cnt,1): sum==0 when cnt==0
    o.x = s.x / fmaxf(c.x, 1.0f) + b;
    o.y = s.y / fmaxf(c.y, 1.0f) + b;
    o.z = s.z / fmaxf(c.z, 1.0f) + b;
    o.w = s.w / fmaxf(c.w, 1.0f) + b;
    ((float4*)out)[i4] = o;
    float4 z = make_float4(0.f, 0.f, 0.f, 0.f);
    *s4 = z;
    *c4 = z;
}

extern "C" void kernel_launch(void* const* d_in, const int* in_sizes, int n_in,
                              void* d_out, int out_size) {
    // Resolve inputs by element count (all distinct) — robust to metadata order.
    const float* feats = 0; const float* mats = 0; const float* lc = 0;
    const int*   mask  = 0; const float* w_cls = 0; const float* b_cls = 0;
    for (int i = 0; i < n_in; i++) {
        switch (in_sizes[i]) {
            case 60211200: feats = (const float*)d_in[i]; break;
            case 96:       mats  = (const float*)d_in[i]; break;
            case 156800:   lc    = (const float*)d_in[i]; break;
            case 39200:    mask  = (const int*)d_in[i];   break;
            case 256:      w_cls = (const float*)d_in[i]; break;
            case 1:        b_cls = (const float*)d_in[i]; break;
        }
    }
    float* out = (float*)d_out;

    dim3 grid((NPIX4 + 127) / 128, NCAM, NCHUNK);  // 77 x 6 x 4 = 1848 blocks
    bev_dot_scatter_kernel<<<grid, 128>>>(feats, mats, lc, mask, w_cls);

    finalize_kernel<<<(NCELL / 4 + 255) / 256, 256>>>(out, b_cls);
}